// round 2
// baseline (speedup 1.0000x reference)
#include <cuda_runtime.h>

#define N_TOTAL 557056
#define NC 64

// Scratch (device globals — no allocation allowed)
__device__ float g_m1[N_TOTAL * NC];
__device__ float g_m2[N_TOTAL * NC];
__device__ float g_hs2[N_TOTAL * NC];

typedef unsigned long long u64t;

__device__ __forceinline__ float4 ld4(const float* p) { return *reinterpret_cast<const float4*>(p); }
__device__ __forceinline__ void st4(float* p, float4 v) { *reinterpret_cast<float4*>(p) = v; }

// ---- packed fp32x2 helpers (sm_100+ : fma.rn.f32x2) ----
__device__ __forceinline__ u64t dup2(float a) {
    u64t r; asm("mov.b64 %0, {%1, %1};" : "=l"(r) : "f"(a)); return r;
}
__device__ __forceinline__ void fma2(u64t& d, u64t a, u64t b) {
    asm("fma.rn.f32x2 %0, %1, %2, %0;" : "+l"(d) : "l"(a), "l"(b));
}
__device__ __forceinline__ float2 up2(u64t v) {
    float2 f; asm("mov.b64 {%0, %1}, %2;" : "=f"(f.x), "=f"(f.y) : "l"(v)); return f;
}

// ---------------------------------------------------------------------------
// 64x64 GEMM tile machinery. 128 threads: ty = tid & 15 (row quad), tx = tid>>4
// (col octet). A tiles column-major in smem: As[k*64 + row].
// B (weight) transposed + XOR-swizzled at 16B granularity:
//   Bs[i*64 + ((((o>>2) ^ (i&15)) << 2) | (o&3))] = W[o*64 + i]
// ---------------------------------------------------------------------------

__device__ __forceinline__ void load_w(float* Bs, const float* __restrict__ W, int tid) {
#pragma unroll
    for (int r = 0; r < 32; r++) {
        int idx = r * 128 + tid;          // 0..4095
        int o = idx >> 6, i = idx & 63;
        int col = ((((o >> 2) ^ (i & 15)) << 2) | (o & 3));
        Bs[i * 64 + col] = W[idx];
    }
}

// stage 64 rows (row-major gmem, 64 floats each) into column-major smem
__device__ __forceinline__ void stage_x(float* S, const float* __restrict__ src, int tid) {
#pragma unroll
    for (int r = 0; r < 8; r++) {
        int idx = r * 128 + tid;          // 0..1023
        int row = idx >> 4, k4 = idx & 15;
        float4 v = ld4(src + row * 64 + k4 * 4);
        S[(k4 * 4 + 0) * 64 + row] = v.x;
        S[(k4 * 4 + 1) * 64 + row] = v.y;
        S[(k4 * 4 + 2) * 64 + row] = v.z;
        S[(k4 * 4 + 3) * 64 + row] = v.w;
    }
}

// acc[ri][cp]: 4 rows (ty*4+ri) x 4 col-pairs (cols tx*8 + cp*2, +1), packed f32x2
__device__ __forceinline__ void gemm64_2(const float* __restrict__ As, const float* __restrict__ Bs,
                                         u64t acc[4][4], int tx, int ty) {
#pragma unroll
    for (int ri = 0; ri < 4; ri++)
#pragma unroll
        for (int cp = 0; cp < 4; cp++) acc[ri][cp] = 0ull;

#pragma unroll 8
    for (int k = 0; k < 64; k++) {
        float4 a = ld4(As + k * 64 + ty * 4);
        int kb = k & 15;
        ulonglong2 b0 = *reinterpret_cast<const ulonglong2*>(Bs + k * 64 + (((tx * 2) ^ kb) << 2));
        ulonglong2 b1 = *reinterpret_cast<const ulonglong2*>(Bs + k * 64 + (((tx * 2 + 1) ^ kb) << 2));
        u64t ad[4] = {dup2(a.x), dup2(a.y), dup2(a.z), dup2(a.w)};
        u64t bp[4] = {b0.x, b0.y, b1.x, b1.y};
#pragma unroll
        for (int ri = 0; ri < 4; ri++)
#pragma unroll
            for (int cp = 0; cp < 4; cp++)
                fma2(acc[ri][cp], ad[ri], bp[cp]);
    }
}

// unpack all accumulators to scalars u[ri][c]  (c = 0..7 within this thread's col octet)
__device__ __forceinline__ void unpack_acc(const u64t acc[4][4], float u[4][8]) {
#pragma unroll
    for (int ri = 0; ri < 4; ri++)
#pragma unroll
        for (int cp = 0; cp < 4; cp++) {
            float2 v = up2(acc[ri][cp]);
            u[ri][cp * 2 + 0] = v.x;
            u[ri][cp * 2 + 1] = v.y;
        }
}

// ---------------------------------------------------------------------------
// Kernel A: x -> m1 (2-layer MLP), m2 (2-layer MLP), skip (Linear) -> g_hs2
// One CTA per 64 rows.
// ---------------------------------------------------------------------------
__global__ void __launch_bounds__(128) kernelA(
    const float* __restrict__ x,
    const float* __restrict__ w_m1, const float* __restrict__ b_m1,
    const float* __restrict__ w_m2, const float* __restrict__ b_m2,
    const float* __restrict__ W_skip, const float* __restrict__ b_skip) {
    __shared__ float Xs[4096];
    __shared__ float Hs[4096];
    __shared__ float Bs[4096];
    int tid = threadIdx.x;
    int ty = tid & 15, tx = tid >> 4;
    long row0 = (long)blockIdx.x * 64;
    u64t acc[4][4];
    float u[4][8];

    stage_x(Xs, x + row0 * 64, tid);
    load_w(Bs, w_m1, tid);
    __syncthreads();

    // ---- m1 layer 0 -> Hs ----
    gemm64_2(Xs, Bs, acc, tx, ty);
    unpack_acc(acc, u);
    __syncthreads();
#pragma unroll
    for (int ci = 0; ci < 8; ci++) {
        int col = tx * 8 + ci;
        float bb = b_m1[col];
        float4 v = make_float4(fmaxf(u[0][ci] + bb, 0.f), fmaxf(u[1][ci] + bb, 0.f),
                               fmaxf(u[2][ci] + bb, 0.f), fmaxf(u[3][ci] + bb, 0.f));
        st4(Hs + col * 64 + ty * 4, v);
    }
    load_w(Bs, w_m1 + 4096, tid);
    __syncthreads();

    // ---- m1 layer 1 -> gmem ----
    gemm64_2(Hs, Bs, acc, tx, ty);
    unpack_acc(acc, u);
#pragma unroll
    for (int ri = 0; ri < 4; ri++) {
        long row = row0 + ty * 4 + ri;
#pragma unroll
        for (int h = 0; h < 2; h++) {
            int cb = tx * 8 + h * 4;
            float4 v;
            v.x = fmaxf(u[ri][h * 4 + 0] + b_m1[64 + cb + 0], 0.f);
            v.y = fmaxf(u[ri][h * 4 + 1] + b_m1[64 + cb + 1], 0.f);
            v.z = fmaxf(u[ri][h * 4 + 2] + b_m1[64 + cb + 2], 0.f);
            v.w = fmaxf(u[ri][h * 4 + 3] + b_m1[64 + cb + 3], 0.f);
            st4(g_m1 + row * 64 + cb, v);
        }
    }
    __syncthreads();

    // ---- m2 layer 0 -> Hs ----
    load_w(Bs, w_m2, tid);
    __syncthreads();
    gemm64_2(Xs, Bs, acc, tx, ty);
    unpack_acc(acc, u);
    __syncthreads();
#pragma unroll
    for (int ci = 0; ci < 8; ci++) {
        int col = tx * 8 + ci;
        float bb = b_m2[col];
        float4 v = make_float4(fmaxf(u[0][ci] + bb, 0.f), fmaxf(u[1][ci] + bb, 0.f),
                               fmaxf(u[2][ci] + bb, 0.f), fmaxf(u[3][ci] + bb, 0.f));
        st4(Hs + col * 64 + ty * 4, v);
    }
    load_w(Bs, w_m2 + 4096, tid);
    __syncthreads();

    // ---- m2 layer 1 -> gmem ----
    gemm64_2(Hs, Bs, acc, tx, ty);
    unpack_acc(acc, u);
#pragma unroll
    for (int ri = 0; ri < 4; ri++) {
        long row = row0 + ty * 4 + ri;
#pragma unroll
        for (int h = 0; h < 2; h++) {
            int cb = tx * 8 + h * 4;
            float4 v;
            v.x = fmaxf(u[ri][h * 4 + 0] + b_m2[64 + cb + 0], 0.f);
            v.y = fmaxf(u[ri][h * 4 + 1] + b_m2[64 + cb + 1], 0.f);
            v.z = fmaxf(u[ri][h * 4 + 2] + b_m2[64 + cb + 2], 0.f);
            v.w = fmaxf(u[ri][h * 4 + 3] + b_m2[64 + cb + 3], 0.f);
            st4(g_m2 + row * 64 + cb, v);
        }
    }
    __syncthreads();

    // ---- skip (no relu) -> g_hs2 ----
    load_w(Bs, W_skip, tid);
    __syncthreads();
    gemm64_2(Xs, Bs, acc, tx, ty);
    unpack_acc(acc, u);
#pragma unroll
    for (int ri = 0; ri < 4; ri++) {
        long row = row0 + ty * 4 + ri;
#pragma unroll
        for (int h = 0; h < 2; h++) {
            int cb = tx * 8 + h * 4;
            float4 v;
            v.x = u[ri][h * 4 + 0] + b_skip[cb + 0];
            v.y = u[ri][h * 4 + 1] + b_skip[cb + 1];
            v.z = u[ri][h * 4 + 2] + b_skip[cb + 2];
            v.w = u[ri][h * 4 + 3] + b_skip[cb + 3];
            st4(g_hs2 + row * 64 + cb, v);
        }
    }
}

// ---------------------------------------------------------------------------
// Kernel B: per-graph-block, per-channel spatial matmul:
//   h[b,i,k,c] = sum_j m1[b,i,j,c] * m2[b,j,k,c];  g_hs2 += h
// Tile: 32 i x 32 k x 16 channels per CTA. 256 threads:
//   is_ = t&7 (i slot), cs = (t>>3)&3 (channel quad), ks = t>>5 (k slot)
// Thread: 4 i x 4 k x 4 CONTIGUOUS channels (c0 + cs*4 .. +3) -> float4/f32x2.
// smem: m1s[i*132 + jj*16 + c]   (stride 132: 16B-aligned, conflict-free)
//       m2s[jj*640 + kk*20 + c]  (stride 20: 16B-aligned, conflict-free)
// bv reads broadcast within warps (ks constant per warp).
// ---------------------------------------------------------------------------
template <int N>
__global__ void __launch_bounds__(256, 2) kernelB(long baseRow) {
    constexpr int TK = (N + 31) / 32;
    __shared__ float m1s[32 * 132];
    __shared__ float m2s[8 * 640];

    int t = threadIdx.x;
    int is_ = t & 7, cs = (t >> 3) & 3, ks = t >> 5;
    int b = blockIdx.x;
    int ti = blockIdx.y / TK, tk = blockIdx.y % TK;
    int c0 = blockIdx.z * 16;
    int i0 = ti * 32, k0 = tk * 32;

    long blkRow = baseRow + (long)b * N * N;
    const float* m1p = g_m1 + blkRow * 64;
    const float* m2p = g_m2 + blkRow * 64;

    u64t acc[4][4][2];
#pragma unroll
    for (int ri = 0; ri < 4; ri++)
#pragma unroll
        for (int rk = 0; rk < 4; rk++) { acc[ri][rk][0] = 0ull; acc[ri][rk][1] = 0ull; }

    int mi = t & 31, mjj = t >> 5;   // m1 staging: (i, jj)
    int mj = t >> 5, mk = t & 31;    // m2 staging: (jj, kk)

    for (int j0 = 0; j0 < N; j0 += 8) {
        __syncthreads();
        // stage m1 tile [32 i][8 jj][16 c]
        {
            float4 v0, v1, v2, v3;
            int i = i0 + mi;
            if (N % 32 == 0 || i < N) {
                const float* src = m1p + ((long)i * N + (j0 + mjj)) * 64 + c0;
                v0 = ld4(src); v1 = ld4(src + 4); v2 = ld4(src + 8); v3 = ld4(src + 12);
            } else {
                v0 = v1 = v2 = v3 = make_float4(0.f, 0.f, 0.f, 0.f);
            }
            float* d = m1s + mi * 132 + mjj * 16;
            st4(d, v0); st4(d + 4, v1); st4(d + 8, v2); st4(d + 12, v3);
        }
        // stage m2 tile [8 jj][32 k][16 c]
        {
            float4 v0, v1, v2, v3;
            int k = k0 + mk;
            if (N % 32 == 0 || k < N) {
                const float* src = m2p + ((long)(j0 + mj) * N + k) * 64 + c0;
                v0 = ld4(src); v1 = ld4(src + 4); v2 = ld4(src + 8); v3 = ld4(src + 12);
            } else {
                v0 = v1 = v2 = v3 = make_float4(0.f, 0.f, 0.f, 0.f);
            }
            float* d = m2s + mj * 640 + mk * 20;
            st4(d, v0); st4(d + 4, v1); st4(d + 8, v2); st4(d + 12, v3);
        }
        __syncthreads();

#pragma unroll
        for (int jj = 0; jj < 8; jj++) {
            const float* ap = m1s + (is_ * 4) * 132 + jj * 16 + cs * 4;
            const float* bp = m2s + jj * 640 + (ks * 4) * 20 + cs * 4;
            ulonglong2 A0 = *reinterpret_cast<const ulonglong2*>(ap);
            ulonglong2 A1 = *reinterpret_cast<const ulonglong2*>(ap + 132);
            ulonglong2 A2 = *reinterpret_cast<const ulonglong2*>(ap + 264);
            ulonglong2 A3 = *reinterpret_cast<const ulonglong2*>(ap + 396);
            ulonglong2 B0 = *reinterpret_cast<const ulonglong2*>(bp);
            ulonglong2 B1 = *reinterpret_cast<const ulonglong2*>(bp + 20);
            ulonglong2 B2 = *reinterpret_cast<const ulonglong2*>(bp + 40);
            ulonglong2 B3 = *reinterpret_cast<const ulonglong2*>(bp + 60);
            ulonglong2 Av[4] = {A0, A1, A2, A3};
            ulonglong2 Bv[4] = {B0, B1, B2, B3};
#pragma unroll
            for (int ri = 0; ri < 4; ri++)
#pragma unroll
                for (int rk = 0; rk < 4; rk++) {
                    fma2(acc[ri][rk][0], Av[ri].x, Bv[rk].x);
                    fma2(acc[ri][rk][1], Av[ri].y, Bv[rk].y);
                }
        }
    }

    // epilogue: g_hs2 (holds skip) += h   (float4 read-modify-write)
#pragma unroll
    for (int ri = 0; ri < 4; ri++) {
        int i = i0 + is_ * 4 + ri;
        if (N % 32 == 0 || i < N) {
#pragma unroll
            for (int rk = 0; rk < 4; rk++) {
                int k = k0 + ks * 4 + rk;
                if (N % 32 == 0 || k < N) {
                    float* p = g_hs2 + (blkRow + (long)i * N + k) * 64 + c0 + cs * 4;
                    float4 r = ld4(p);
                    float2 lo = up2(acc[ri][rk][0]);
                    float2 hi = up2(acc[ri][rk][1]);
                    r.x += lo.x; r.y += lo.y; r.z += hi.x; r.w += hi.y;
                    st4(p, r);
                }
            }
        }
    }
}

// ---------------------------------------------------------------------------
// Kernel C: hs2 -> Linear+BN+ReLU -> Linear+BN+ReLU -> +hs2 -> out
// ---------------------------------------------------------------------------
__global__ void __launch_bounds__(128) kernelC(
    const float* __restrict__ W_u1, const float* __restrict__ b_u1,
    const float* __restrict__ g1, const float* __restrict__ beta1,
    const float* __restrict__ rm1, const float* __restrict__ rv1,
    const float* __restrict__ W_u2, const float* __restrict__ b_u2,
    const float* __restrict__ g2, const float* __restrict__ beta2,
    const float* __restrict__ rm2, const float* __restrict__ rv2,
    float* __restrict__ out) {
    __shared__ float Xs[4096];
    __shared__ float Hs[4096];
    __shared__ float Bs[4096];
    int tid = threadIdx.x;
    int ty = tid & 15, tx = tid >> 4;
    long row0 = (long)blockIdx.x * 64;
    u64t acc[4][4];
    float u[4][8];

    stage_x(Xs, g_hs2 + row0 * 64, tid);
    load_w(Bs, W_u1, tid);
    __syncthreads();

    // layer u1: Linear + BN + ReLU -> Hs
    gemm64_2(Xs, Bs, acc, tx, ty);
    unpack_acc(acc, u);
    __syncthreads();
#pragma unroll
    for (int ci = 0; ci < 8; ci++) {
        int col = tx * 8 + ci;
        float sc = g1[col] * rsqrtf(rv1[col] + 1e-5f);
        float sh = beta1[col] - rm1[col] * sc;
        float bb = b_u1[col];
        float4 v = make_float4(fmaxf((u[0][ci] + bb) * sc + sh, 0.f),
                               fmaxf((u[1][ci] + bb) * sc + sh, 0.f),
                               fmaxf((u[2][ci] + bb) * sc + sh, 0.f),
                               fmaxf((u[3][ci] + bb) * sc + sh, 0.f));
        st4(Hs + col * 64 + ty * 4, v);
    }
    load_w(Bs, W_u2, tid);
    __syncthreads();

    // layer u2: Linear + BN + ReLU + residual(hs2) -> out
    gemm64_2(Hs, Bs, acc, tx, ty);
    unpack_acc(acc, u);
    float y[4][8];
#pragma unroll
    for (int ci = 0; ci < 8; ci++) {
        int col = tx * 8 + ci;
        float sc = g2[col] * rsqrtf(rv2[col] + 1e-5f);
        float sh = beta2[col] - rm2[col] * sc;
        float bb = b_u2[col];
        float4 xv = ld4(Xs + col * 64 + ty * 4);
        y[0][ci] = fmaxf((u[0][ci] + bb) * sc + sh, 0.f) + xv.x;
        y[1][ci] = fmaxf((u[1][ci] + bb) * sc + sh, 0.f) + xv.y;
        y[2][ci] = fmaxf((u[2][ci] + bb) * sc + sh, 0.f) + xv.z;
        y[3][ci] = fmaxf((u[3][ci] + bb) * sc + sh, 0.f) + xv.w;
    }
#pragma unroll
    for (int ri = 0; ri < 4; ri++) {
        long row = row0 + ty * 4 + ri;
#pragma unroll
        for (int h = 0; h < 2; h++) {
            int cb = tx * 8 + h * 4;
            st4(out + row * 64 + cb,
                make_float4(y[ri][h * 4 + 0], y[ri][h * 4 + 1],
                            y[ri][h * 4 + 2], y[ri][h * 4 + 3]));
        }
    }
}

// ---------------------------------------------------------------------------
extern "C" void kernel_launch(void* const* d_in, const int* in_sizes, int n_in,
                              void* d_out, int out_size) {
    (void)in_sizes; (void)n_in; (void)out_size;
    const float* x      = (const float*)d_in[0];
    const float* w_m1   = (const float*)d_in[1];
    const float* b_m1   = (const float*)d_in[2];
    const float* w_m2   = (const float*)d_in[3];
    const float* b_m2   = (const float*)d_in[4];
    const float* W_skip = (const float*)d_in[5];
    const float* b_skip = (const float*)d_in[6];
    const float* W_u1   = (const float*)d_in[7];
    const float* b_u1   = (const float*)d_in[8];
    const float* g1     = (const float*)d_in[9];
    const float* beta1  = (const float*)d_in[10];
    const float* rm1    = (const float*)d_in[11];
    const float* rv1    = (const float*)d_in[12];
    const float* W_u2   = (const float*)d_in[13];
    const float* b_u2   = (const float*)d_in[14];
    const float* g2     = (const float*)d_in[15];
    const float* beta2  = (const float*)d_in[16];
    const float* rm2    = (const float*)d_in[17];
    const float* rv2    = (const float*)d_in[18];
    float* out = (float*)d_out;

    kernelA<<<N_TOTAL / 64, 128>>>(x, w_m1, b_m1, w_m2, b_m2, W_skip, b_skip);

    // BLOCKS = [(128,32),(64,48),(32,64),(16,96)], row bases 0/131072/278528/409600
    kernelB<32><<<dim3(128, 1, 4), 256>>>(0L);
    kernelB<48><<<dim3(64, 4, 4), 256>>>(131072L);
    kernelB<64><<<dim3(32, 4, 4), 256>>>(278528L);
    kernelB<96><<<dim3(16, 9, 4), 256>>>(409600L);

    kernelC<<<N_TOTAL / 64, 128>>>(W_u1, b_u1, g1, beta1, rm1, rv1,
                                   W_u2, b_u2, g2, beta2, rm2, rv2, out);
}

// round 4
// speedup vs baseline: 1.9678x; 1.9678x over previous
#include <cuda_runtime.h>
#include <cuda_bf16.h>
#include <cstdint>

#define N_TOTAL 557056
#define NC 64

// Scratch (device globals — no allocation allowed)
__device__ float g_m1[N_TOTAL * NC];
__device__ float g_m2[N_TOTAL * NC];
__device__ float g_hs2[N_TOTAL * NC];
// Pre-split, pre-swizzled weights: 7 matrices x 4096 bf16 (hi and lo), SW128 layout
__device__ uint4 g_wh4[7 * 512];
__device__ uint4 g_wl4[7 * 512];

__device__ __forceinline__ float4 ld4(const float* p) { return *reinterpret_cast<const float4*>(p); }
__device__ __forceinline__ void st4(float* p, float4 v) { *reinterpret_cast<float4*>(p) = v; }

__device__ __forceinline__ uint32_t smem_to_u32(const void* smem_ptr) {
    uint32_t addr;
    asm("{ .reg .u64 tmp; cvta.to.shared.u64 tmp, %1; cvt.u32.u64 %0, tmp; }"
        : "=r"(addr) : "l"(smem_ptr));
    return addr;
}
__device__ __forceinline__ uint32_t swz(uint32_t off) { return off ^ ((off >> 3) & 0x70); }

// ===================== mma.sync / ldmatrix machinery =======================
__device__ __forceinline__ void ldsm_x4(uint32_t r[4], uint32_t addr) {
    asm volatile("ldmatrix.sync.aligned.m8n8.x4.shared.b16 {%0,%1,%2,%3}, [%4];"
                 : "=r"(r[0]), "=r"(r[1]), "=r"(r[2]), "=r"(r[3]) : "r"(addr));
}
__device__ __forceinline__ void mma16816(float c[4], const uint32_t a[4], const uint32_t b[2]) {
    asm volatile("mma.sync.aligned.m16n8k16.row.col.f32.bf16.bf16.f32 "
                 "{%0,%1,%2,%3}, {%4,%5,%6,%7}, {%8,%9}, {%0,%1,%2,%3};"
                 : "+f"(c[0]), "+f"(c[1]), "+f"(c[2]), "+f"(c[3])
                 : "r"(a[0]), "r"(a[1]), "r"(a[2]), "r"(a[3]), "r"(b[0]), "r"(b[1]));
}

// bf16 two-term split of a float pair
__device__ __forceinline__ void split2(float a, float b, uint32_t& h, uint32_t& l) {
    __nv_bfloat162 hh = __floats2bfloat162_rn(a, b);
    float la = a - __bfloat162float(hh.x);
    float lb = b - __bfloat162float(hh.y);
    __nv_bfloat162 ll = __floats2bfloat162_rn(la, lb);
    h = *reinterpret_cast<uint32_t*>(&hh);
    l = *reinterpret_cast<uint32_t*>(&ll);
}

// ===================== SMEM layout for kernels A and C =====================
// X/H tiles: 128 rows x 64 bf16 (128B rows, SW128). W tiles: 64 rows x 128B.
#define OXH 0
#define OXL 16384
#define OHH 32768
#define OHL 49152
#define OBH 65536
#define OBL 73728
#define OPAR 81920
#define SMEM_BYTES 83968

// load B fragments (8 n-tiles) for one k16 step from a 64x64 bf16 SW128 tile
__device__ __forceinline__ void loadB(uint32_t bf[16], uint32_t sbW, int ks, int lane) {
    int rowB = (lane & 7) + ((lane >> 4) << 3);
    int chB = ks * 2 + ((lane >> 3) & 1);
#pragma unroll
    for (int t = 0; t < 4; t++) {
        uint32_t off = swz((uint32_t)((t * 16 + rowB) * 128 + chB * 16));
        ldsm_x4(bf + 4 * t, sbW + off);
    }
}

// warp GEMM: rows [wid*32, wid*32+32) x 64 cols, K=64, 3-term bf16 split
__device__ __forceinline__ void warp_gemm(uint32_t sb, int aHi, int aLo,
                                          float acc[2][8][4], int wid, int lane) {
#pragma unroll
    for (int m = 0; m < 2; m++)
#pragma unroll
        for (int nt = 0; nt < 8; nt++)
#pragma unroll
            for (int q = 0; q < 4; q++) acc[m][nt][q] = 0.f;

#pragma unroll
    for (int ks = 0; ks < 4; ks++) {
        uint32_t ah[2][4], al[2][4], bf[16];
        int rowA = wid * 32 + (lane & 15);
        int chA = ks * 2 + (lane >> 4);
        uint32_t offA0 = swz((uint32_t)(rowA * 128 + chA * 16));
        uint32_t offA1 = swz((uint32_t)((rowA + 16) * 128 + chA * 16));
        ldsm_x4(ah[0], sb + aHi + offA0);
        ldsm_x4(ah[1], sb + aHi + offA1);
        ldsm_x4(al[0], sb + aLo + offA0);
        ldsm_x4(al[1], sb + aLo + offA1);
        // term 1+2: (Ah + Al) * Wh
        loadB(bf, sb + OBH, ks, lane);
#pragma unroll
        for (int m = 0; m < 2; m++)
#pragma unroll
            for (int p = 0; p < 4; p++) {
                mma16816(acc[m][2 * p], ah[m], &bf[4 * p]);
                mma16816(acc[m][2 * p], al[m], &bf[4 * p]);
                mma16816(acc[m][2 * p + 1], ah[m], &bf[4 * p + 2]);
                mma16816(acc[m][2 * p + 1], al[m], &bf[4 * p + 2]);
            }
        // term 3: Ah * Wl
        loadB(bf, sb + OBL, ks, lane);
#pragma unroll
        for (int m = 0; m < 2; m++)
#pragma unroll
            for (int p = 0; p < 4; p++) {
                mma16816(acc[m][2 * p], ah[m], &bf[4 * p]);
                mma16816(acc[m][2 * p + 1], ah[m], &bf[4 * p + 2]);
            }
    }
}

// copy pre-swizzled weight matrix m into OBH/OBL (8KB each)
__device__ __forceinline__ void copyW(char* sm, int m, int tid) {
#pragma unroll
    for (int i = 0; i < 4; i++) {
        int idx = i * 128 + tid;
        reinterpret_cast<uint4*>(sm + OBH)[idx] = g_wh4[m * 512 + idx];
        reinterpret_cast<uint4*>(sm + OBL)[idx] = g_wl4[m * 512 + idx];
    }
}

// convert 128 rows x 64 fp32 (row-major gmem) -> bf16 hi/lo SW128 smem tiles
__device__ __forceinline__ void convertX(char* sm, const float* __restrict__ src, int tid) {
#pragma unroll
    for (int i = 0; i < 8; i++) {
        int idx = i * 128 + tid;
        int r = idx >> 3, g = idx & 7;
        const float* p = src + r * 64 + g * 8;
        float4 f0 = ld4(p), f1 = ld4(p + 4);
        float vv[8] = {f0.x, f0.y, f0.z, f0.w, f1.x, f1.y, f1.z, f1.w};
        uint32_t hw[4], lw[4];
#pragma unroll
        for (int q = 0; q < 4; q++) split2(vv[2 * q], vv[2 * q + 1], hw[q], lw[q]);
        uint32_t off = swz((uint32_t)(r * 128 + g * 16));
        *reinterpret_cast<uint4*>(sm + OXH + off) = make_uint4(hw[0], hw[1], hw[2], hw[3]);
        *reinterpret_cast<uint4*>(sm + OXL + off) = make_uint4(lw[0], lw[1], lw[2], lw[3]);
    }
}

// ========================== setup: split weights ===========================
__global__ void kernelW(const float* __restrict__ w_m1, const float* __restrict__ w_m2,
                        const float* __restrict__ W_skip, const float* __restrict__ W_u1,
                        const float* __restrict__ W_u2) {
    int m = blockIdx.y;
    int idx = blockIdx.x * 256 + threadIdx.x;   // 0..4095
    const float* W;
    switch (m) {
        case 0: W = w_m1; break;
        case 1: W = w_m1 + 4096; break;
        case 2: W = w_m2; break;
        case 3: W = w_m2 + 4096; break;
        case 4: W = W_skip; break;
        case 5: W = W_u1; break;
        default: W = W_u2; break;
    }
    float v = W[idx];
    int o = idx >> 6, k = idx & 63;
    __nv_bfloat16 h = __float2bfloat16(v);
    __nv_bfloat16 l = __float2bfloat16(v - __bfloat162float(h));
    uint32_t eoff = swz((uint32_t)(o * 128 + k * 2)) >> 1;
    reinterpret_cast<__nv_bfloat16*>(g_wh4)[m * 4096 + eoff] = h;
    reinterpret_cast<__nv_bfloat16*>(g_wl4)[m * 4096 + eoff] = l;
}

// ======= epilogue helpers (fragment layout: rows g,g+8; col pairs) =========
// store acc (+bias, relu) as split bf16 into HH/HL
__device__ __forceinline__ void epiH(char* sm, const float acc[2][8][4], const float* bias,
                                     int wid, int lane) {
    int g = lane >> 2, cb = (lane & 3) * 4;
#pragma unroll
    for (int m = 0; m < 2; m++)
#pragma unroll
        for (int rs = 0; rs < 2; rs++) {
            int row = wid * 32 + m * 16 + rs * 8 + g;
#pragma unroll
            for (int nt = 0; nt < 8; nt++) {
                int c = nt * 8 + (lane & 3) * 2;
                float v0 = fmaxf(acc[m][nt][rs * 2 + 0] + bias[c], 0.f);
                float v1 = fmaxf(acc[m][nt][rs * 2 + 1] + bias[c + 1], 0.f);
                uint32_t h, l;
                split2(v0, v1, h, l);
                uint32_t off = swz((uint32_t)(row * 128 + nt * 16 + cb));
                *reinterpret_cast<uint32_t*>(sm + OHH + off) = h;
                *reinterpret_cast<uint32_t*>(sm + OHL + off) = l;
            }
        }
}

// store acc (+bias, optional relu) to gmem
template <bool RELU>
__device__ __forceinline__ void epiG(float* __restrict__ dst, long row0,
                                     const float acc[2][8][4], const float* bias,
                                     int wid, int lane) {
    int g = lane >> 2;
#pragma unroll
    for (int m = 0; m < 2; m++)
#pragma unroll
        for (int rs = 0; rs < 2; rs++) {
            long row = row0 + wid * 32 + m * 16 + rs * 8 + g;
#pragma unroll
            for (int nt = 0; nt < 8; nt++) {
                int c = nt * 8 + (lane & 3) * 2;
                float v0 = acc[m][nt][rs * 2 + 0] + bias[c];
                float v1 = acc[m][nt][rs * 2 + 1] + bias[c + 1];
                if (RELU) { v0 = fmaxf(v0, 0.f); v1 = fmaxf(v1, 0.f); }
                *reinterpret_cast<float2*>(dst + row * 64 + c) = make_float2(v0, v1);
            }
        }
}

// =============== Kernel A: x -> m1, m2 (2-layer MLPs), skip ================
__global__ void __launch_bounds__(128) kernelA(
    const float* __restrict__ x,
    const float* __restrict__ b_m1, const float* __restrict__ b_m2,
    const float* __restrict__ b_skip) {
    extern __shared__ char sm[];
    uint32_t sb = smem_to_u32(sm);
    int tid = threadIdx.x, wid = tid >> 5, lane = tid & 31;
    long row0 = (long)blockIdx.x * 128;
    float* par = reinterpret_cast<float*>(sm + OPAR);

    if (tid < 64) {
        par[tid] = b_m1[tid];
        par[64 + tid] = b_m1[64 + tid];
        par[128 + tid] = b_m2[tid];
        par[192 + tid] = b_m2[64 + tid];
        par[256 + tid] = b_skip[tid];
    }
    convertX(sm, x + row0 * 64, tid);
    copyW(sm, 0, tid);
    __syncthreads();

    float acc[2][8][4];

    // GEMM1: X @ Wm1_0 -> H (relu)
    warp_gemm(sb, OXH, OXL, acc, wid, lane);
    __syncthreads();
    epiH(sm, acc, par, wid, lane);
    copyW(sm, 1, tid);
    __syncthreads();

    // GEMM2: H @ Wm1_1 -> g_m1 (relu)
    warp_gemm(sb, OHH, OHL, acc, wid, lane);
    __syncthreads();
    epiG<true>(g_m1, row0, acc, par + 64, wid, lane);
    copyW(sm, 2, tid);
    __syncthreads();

    // GEMM3: X @ Wm2_0 -> H (relu)
    warp_gemm(sb, OXH, OXL, acc, wid, lane);
    __syncthreads();
    epiH(sm, acc, par + 128, wid, lane);
    copyW(sm, 3, tid);
    __syncthreads();

    // GEMM4: H @ Wm2_1 -> g_m2 (relu)
    warp_gemm(sb, OHH, OHL, acc, wid, lane);
    __syncthreads();
    epiG<true>(g_m2, row0, acc, par + 192, wid, lane);
    copyW(sm, 4, tid);
    __syncthreads();

    // GEMM5: X @ W_skip -> g_hs2 (no relu)
    warp_gemm(sb, OXH, OXL, acc, wid, lane);
    epiG<false>(g_hs2, row0, acc, par + 256, wid, lane);
}

// ---------------------------------------------------------------------------
// Kernel B (R1 version): per-graph-block, per-channel spatial matmul
// ---------------------------------------------------------------------------
template <int N>
__global__ void __launch_bounds__(256) kernelB(long baseRow) {
    constexpr int TK = (N + 31) / 32;
    __shared__ float m1s[32 * 129];
    __shared__ float m2s[8 * 544];

    int t = threadIdx.x;
    int cs = t & 3, is_ = (t >> 2) & 7, ks = t >> 5;
    int b = blockIdx.x;
    int ti = blockIdx.y / TK, tk = blockIdx.y % TK;
    int c0 = blockIdx.z * 16;
    int i0 = ti * 32, k0 = tk * 32;

    long blkRow = baseRow + (long)b * N * N;
    const float* m1p = g_m1 + blkRow * 64;
    const float* m2p = g_m2 + blkRow * 64;

    float acc[4][4][4];
#pragma unroll
    for (int ri = 0; ri < 4; ri++)
#pragma unroll
        for (int rk = 0; rk < 4; rk++)
#pragma unroll
            for (int q = 0; q < 4; q++) acc[ri][rk][q] = 0.f;

    int li = t >> 3, lj = t & 7;
    int mj = t >> 5, mk = t & 31;

    for (int j0 = 0; j0 < N; j0 += 8) {
        __syncthreads();
        {
            float4 v0, v1, v2, v3;
            int i = i0 + li;
            if (N % 32 == 0 || i < N) {
                const float* src = m1p + ((long)i * N + (j0 + lj)) * 64 + c0;
                v0 = ld4(src); v1 = ld4(src + 4); v2 = ld4(src + 8); v3 = ld4(src + 12);
            } else {
                v0 = v1 = v2 = v3 = make_float4(0.f, 0.f, 0.f, 0.f);
            }
            float* dd = m1s + li * 129 + lj * 16;
            dd[0] = v0.x;  dd[1] = v0.y;  dd[2] = v0.z;  dd[3] = v0.w;
            dd[4] = v1.x;  dd[5] = v1.y;  dd[6] = v1.z;  dd[7] = v1.w;
            dd[8] = v2.x;  dd[9] = v2.y;  dd[10] = v2.z; dd[11] = v2.w;
            dd[12] = v3.x; dd[13] = v3.y; dd[14] = v3.z; dd[15] = v3.w;
        }
        {
            float4 v0, v1, v2, v3;
            int k = k0 + mk;
            if (N % 32 == 0 || k < N) {
                const float* src = m2p + ((long)(j0 + mj) * N + k) * 64 + c0;
                v0 = ld4(src); v1 = ld4(src + 4); v2 = ld4(src + 8); v3 = ld4(src + 12);
            } else {
                v0 = v1 = v2 = v3 = make_float4(0.f, 0.f, 0.f, 0.f);
            }
            float* dd = m2s + mj * 544 + mk * 17;
            dd[0] = v0.x;  dd[1] = v0.y;  dd[2] = v0.z;  dd[3] = v0.w;
            dd[4] = v1.x;  dd[5] = v1.y;  dd[6] = v1.z;  dd[7] = v1.w;
            dd[8] = v2.x;  dd[9] = v2.y;  dd[10] = v2.z; dd[11] = v2.w;
            dd[12] = v3.x; dd[13] = v3.y; dd[14] = v3.z; dd[15] = v3.w;
        }
        __syncthreads();

#pragma unroll
        for (int jj = 0; jj < 8; jj++) {
            float av[4][4], bv[4][4];
#pragma unroll
            for (int ri = 0; ri < 4; ri++)
#pragma unroll
                for (int q = 0; q < 4; q++)
                    av[ri][q] = m1s[(is_ * 4 + ri) * 129 + jj * 16 + cs + 4 * q];
#pragma unroll
            for (int rk = 0; rk < 4; rk++)
#pragma unroll
                for (int q = 0; q < 4; q++)
                    bv[rk][q] = m2s[jj * 544 + (ks * 4 + rk) * 17 + cs + 4 * q];
#pragma unroll
            for (int ri = 0; ri < 4; ri++)
#pragma unroll
                for (int rk = 0; rk < 4; rk++)
#pragma unroll
                    for (int q = 0; q < 4; q++)
                        acc[ri][rk][q] += av[ri][q] * bv[rk][q];
        }
    }

#pragma unroll
    for (int ri = 0; ri < 4; ri++) {
        int i = i0 + is_ * 4 + ri;
        if (N % 32 == 0 || i < N) {
#pragma unroll
            for (int rk = 0; rk < 4; rk++) {
                int k = k0 + ks * 4 + rk;
                if (N % 32 == 0 || k < N) {
                    float* p = g_hs2 + (blkRow + (long)i * N + k) * 64 + c0 + cs;
#pragma unroll
                    for (int q = 0; q < 4; q++)
                        p[4 * q] += acc[ri][rk][q];
                }
            }
        }
    }
}

// ======== Kernel C: hs2 -> Lin+BN+ReLU -> Lin+BN+ReLU -> +hs2 -> out ========
__global__ void __launch_bounds__(128) kernelC(
    const float* __restrict__ b_u1, const float* __restrict__ g1,
    const float* __restrict__ beta1, const float* __restrict__ rm1,
    const float* __restrict__ rv1,
    const float* __restrict__ b_u2, const float* __restrict__ g2,
    const float* __restrict__ beta2, const float* __restrict__ rm2,
    const float* __restrict__ rv2,
    float* __restrict__ out) {
    extern __shared__ char sm[];
    uint32_t sb = smem_to_u32(sm);
    int tid = threadIdx.x, wid = tid >> 5, lane = tid & 31;
    long row0 = (long)blockIdx.x * 128;
    float* par = reinterpret_cast<float*>(sm + OPAR);

    if (tid < 64) {
        par[tid] = b_u1[tid];
        float sc1 = g1[tid] * rsqrtf(rv1[tid] + 1e-5f);
        par[64 + tid] = sc1;
        par[128 + tid] = beta1[tid] - rm1[tid] * sc1;
        par[192 + tid] = b_u2[tid];
        float sc2 = g2[tid] * rsqrtf(rv2[tid] + 1e-5f);
        par[256 + tid] = sc2;
        par[320 + tid] = beta2[tid] - rm2[tid] * sc2;
    }
    convertX(sm, g_hs2 + row0 * 64, tid);
    copyW(sm, 5, tid);
    __syncthreads();

    float acc[2][8][4];

    // GEMM1: hs2 @ W_u1 -> H = relu(bn1(. + b_u1))
    warp_gemm(sb, OXH, OXL, acc, wid, lane);
    __syncthreads();
    {
        int g = lane >> 2, cb = (lane & 3) * 4;
#pragma unroll
        for (int m = 0; m < 2; m++)
#pragma unroll
            for (int rs = 0; rs < 2; rs++) {
                int row = wid * 32 + m * 16 + rs * 8 + g;
#pragma unroll
                for (int nt = 0; nt < 8; nt++) {
                    int c = nt * 8 + (lane & 3) * 2;
                    float v0 = fmaxf((acc[m][nt][rs * 2 + 0] + par[c]) * par[64 + c] + par[128 + c], 0.f);
                    float v1 = fmaxf((acc[m][nt][rs * 2 + 1] + par[c + 1]) * par[64 + c + 1] + par[128 + c + 1], 0.f);
                    uint32_t h, l;
                    split2(v0, v1, h, l);
                    uint32_t off = swz((uint32_t)(row * 128 + nt * 16 + cb));
                    *reinterpret_cast<uint32_t*>(sm + OHH + off) = h;
                    *reinterpret_cast<uint32_t*>(sm + OHL + off) = l;
                }
            }
    }
    copyW(sm, 6, tid);
    __syncthreads();

    // GEMM2: H @ W_u2 -> out = relu(bn2(. + b_u2)) + hs2
    warp_gemm(sb, OHH, OHL, acc, wid, lane);
    {
        int g = lane >> 2, cb = (lane & 3) * 4;
#pragma unroll
        for (int m = 0; m < 2; m++)
#pragma unroll
            for (int rs = 0; rs < 2; rs++) {
                int row = wid * 32 + m * 16 + rs * 8 + g;
                long grow = row0 + row;
#pragma unroll
                for (int nt = 0; nt < 8; nt++) {
                    int c = nt * 8 + (lane & 3) * 2;
                    float u0 = fmaxf((acc[m][nt][rs * 2 + 0] + par[192 + c]) * par[256 + c] + par[320 + c], 0.f);
                    float u1 = fmaxf((acc[m][nt][rs * 2 + 1] + par[192 + c + 1]) * par[256 + c + 1] + par[320 + c + 1], 0.f);
                    // hs2 residual reconstructed from hi+lo bf16 tiles
                    uint32_t off = swz((uint32_t)(row * 128 + nt * 16 + cb));
                    uint32_t xh = *reinterpret_cast<uint32_t*>(sm + OXH + off);
                    uint32_t xl = *reinterpret_cast<uint32_t*>(sm + OXL + off);
                    float2 h2 = __bfloat1622float2(*reinterpret_cast<__nv_bfloat162*>(&xh));
                    float2 l2 = __bfloat1622float2(*reinterpret_cast<__nv_bfloat162*>(&xl));
                    *reinterpret_cast<float2*>(out + grow * 64 + c) =
                        make_float2(u0 + (h2.x + l2.x), u1 + (h2.y + l2.y));
                }
            }
    }
}

// ---------------------------------------------------------------------------
extern "C" void kernel_launch(void* const* d_in, const int* in_sizes, int n_in,
                              void* d_out, int out_size) {
    (void)in_sizes; (void)n_in; (void)out_size;
    const float* x      = (const float*)d_in[0];
    const float* w_m1   = (const float*)d_in[1];
    const float* b_m1   = (const float*)d_in[2];
    const float* w_m2   = (const float*)d_in[3];
    const float* b_m2   = (const float*)d_in[4];
    const float* W_skip = (const float*)d_in[5];
    const float* b_skip = (const float*)d_in[6];
    const float* W_u1   = (const float*)d_in[7];
    const float* b_u1   = (const float*)d_in[8];
    const float* g1     = (const float*)d_in[9];
    const float* beta1  = (const float*)d_in[10];
    const float* rm1    = (const float*)d_in[11];
    const float* rv1    = (const float*)d_in[12];
    const float* W_u2   = (const float*)d_in[13];
    const float* b_u2   = (const float*)d_in[14];
    const float* g2     = (const float*)d_in[15];
    const float* beta2  = (const float*)d_in[16];
    const float* rm2    = (const float*)d_in[17];
    const float* rv2    = (const float*)d_in[18];
    float* out = (float*)d_out;

    cudaFuncSetAttribute(kernelA, cudaFuncAttributeMaxDynamicSharedMemorySize, SMEM_BYTES);
    cudaFuncSetAttribute(kernelC, cudaFuncAttributeMaxDynamicSharedMemorySize, SMEM_BYTES);

    kernelW<<<dim3(16, 7), 256>>>(w_m1, w_m2, W_skip, W_u1, W_u2);

    kernelA<<<N_TOTAL / 128, 128, SMEM_BYTES>>>(x, b_m1, b_m2, b_skip);

    // BLOCKS = [(128,32),(64,48),(32,64),(16,96)], row bases 0/131072/278528/409600
    kernelB<32><<<dim3(128, 1, 4), 256>>>(0L);
    kernelB<48><<<dim3(64, 4, 4), 256>>>(131072L);
    kernelB<64><<<dim3(32, 4, 4), 256>>>(278528L);
    kernelB<96><<<dim3(16, 9, 4), 256>>>(409600L);

    kernelC<<<N_TOTAL / 128, 128, SMEM_BYTES>>>(b_u1, g1, beta1, rm1, rv1,
                                                b_u2, g2, beta2, rm2, rv2, out);
}

// round 5
// speedup vs baseline: 2.4047x; 1.2220x over previous
#include <cuda_runtime.h>
#include <cuda_bf16.h>
#include <cstdint>

#define N_TOTAL 557056
#define NC 64

// Scratch (device globals — no allocation allowed)
// g_m1/g_m2 now hold the MLP outputs TRANSPOSED per graph-block: (c, i*n+j), fp32
__device__ float g_m1[N_TOTAL * NC];
__device__ float g_m2[N_TOTAL * NC];
__device__ float g_hs2[N_TOTAL * NC];
// Pre-split, pre-swizzled weights: 7 matrices x 4096 bf16 (hi and lo), SW128 layout
__device__ uint4 g_wh4[7 * 512];
__device__ uint4 g_wl4[7 * 512];

__device__ __forceinline__ float4 ld4(const float* p) { return *reinterpret_cast<const float4*>(p); }
__device__ __forceinline__ void st4(float* p, float4 v) { *reinterpret_cast<float4*>(p) = v; }

__device__ __forceinline__ uint32_t smem_to_u32(const void* smem_ptr) {
    uint32_t addr;
    asm("{ .reg .u64 tmp; cvta.to.shared.u64 tmp, %1; cvt.u32.u64 %0, tmp; }"
        : "=r"(addr) : "l"(smem_ptr));
    return addr;
}
__device__ __forceinline__ uint32_t swz(uint32_t off) { return off ^ ((off >> 3) & 0x70); }

// ===================== mma.sync / ldmatrix machinery =======================
__device__ __forceinline__ void ldsm_x4(uint32_t r[4], uint32_t addr) {
    asm volatile("ldmatrix.sync.aligned.m8n8.x4.shared.b16 {%0,%1,%2,%3}, [%4];"
                 : "=r"(r[0]), "=r"(r[1]), "=r"(r[2]), "=r"(r[3]) : "r"(addr));
}
__device__ __forceinline__ void ldsm_x4_t(uint32_t r[4], uint32_t addr) {
    asm volatile("ldmatrix.sync.aligned.m8n8.x4.trans.shared.b16 {%0,%1,%2,%3}, [%4];"
                 : "=r"(r[0]), "=r"(r[1]), "=r"(r[2]), "=r"(r[3]) : "r"(addr));
}
__device__ __forceinline__ void mma16816(float c[4], const uint32_t a[4], const uint32_t b[2]) {
    asm volatile("mma.sync.aligned.m16n8k16.row.col.f32.bf16.bf16.f32 "
                 "{%0,%1,%2,%3}, {%4,%5,%6,%7}, {%8,%9}, {%0,%1,%2,%3};"
                 : "+f"(c[0]), "+f"(c[1]), "+f"(c[2]), "+f"(c[3])
                 : "r"(a[0]), "r"(a[1]), "r"(a[2]), "r"(a[3]), "r"(b[0]), "r"(b[1]));
}

// bf16 two-term split of a float pair
__device__ __forceinline__ void split2(float a, float b, uint32_t& h, uint32_t& l) {
    __nv_bfloat162 hh = __floats2bfloat162_rn(a, b);
    float la = a - __bfloat162float(hh.x);
    float lb = b - __bfloat162float(hh.y);
    __nv_bfloat162 ll = __floats2bfloat162_rn(la, lb);
    h = *reinterpret_cast<uint32_t*>(&hh);
    l = *reinterpret_cast<uint32_t*>(&ll);
}

// ===================== SMEM layout for kernels A and C =====================
#define OXH 0
#define OXL 16384
#define OHH 32768
#define OHL 49152
#define OBH 65536
#define OBL 73728
#define OPAR 81920
#define SMEM_BYTES 83968

// load B fragments (8 n-tiles) for one k16 step from a 64x64 bf16 SW128 tile
__device__ __forceinline__ void loadB(uint32_t bf[16], uint32_t sbW, int ks, int lane) {
    int rowB = (lane & 7) + ((lane >> 4) << 3);
    int chB = ks * 2 + ((lane >> 3) & 1);
#pragma unroll
    for (int t = 0; t < 4; t++) {
        uint32_t off = swz((uint32_t)((t * 16 + rowB) * 128 + chB * 16));
        ldsm_x4(bf + 4 * t, sbW + off);
    }
}

// warp GEMM: rows [wid*32, wid*32+32) x 64 cols, K=64, 3-term bf16 split
__device__ __forceinline__ void warp_gemm(uint32_t sb, int aHi, int aLo,
                                          float acc[2][8][4], int wid, int lane) {
#pragma unroll
    for (int m = 0; m < 2; m++)
#pragma unroll
        for (int nt = 0; nt < 8; nt++)
#pragma unroll
            for (int q = 0; q < 4; q++) acc[m][nt][q] = 0.f;

#pragma unroll
    for (int ks = 0; ks < 4; ks++) {
        uint32_t ah[2][4], al[2][4], bf[16];
        int rowA = wid * 32 + (lane & 15);
        int chA = ks * 2 + (lane >> 4);
        uint32_t offA0 = swz((uint32_t)(rowA * 128 + chA * 16));
        uint32_t offA1 = swz((uint32_t)((rowA + 16) * 128 + chA * 16));
        ldsm_x4(ah[0], sb + aHi + offA0);
        ldsm_x4(ah[1], sb + aHi + offA1);
        ldsm_x4(al[0], sb + aLo + offA0);
        ldsm_x4(al[1], sb + aLo + offA1);
        loadB(bf, sb + OBH, ks, lane);
#pragma unroll
        for (int m = 0; m < 2; m++)
#pragma unroll
            for (int p = 0; p < 4; p++) {
                mma16816(acc[m][2 * p], ah[m], &bf[4 * p]);
                mma16816(acc[m][2 * p], al[m], &bf[4 * p]);
                mma16816(acc[m][2 * p + 1], ah[m], &bf[4 * p + 2]);
                mma16816(acc[m][2 * p + 1], al[m], &bf[4 * p + 2]);
            }
        loadB(bf, sb + OBL, ks, lane);
#pragma unroll
        for (int m = 0; m < 2; m++)
#pragma unroll
            for (int p = 0; p < 4; p++) {
                mma16816(acc[m][2 * p], ah[m], &bf[4 * p]);
                mma16816(acc[m][2 * p + 1], ah[m], &bf[4 * p + 2]);
            }
    }
}

// copy pre-swizzled weight matrix m into OBH/OBL (8KB each)
__device__ __forceinline__ void copyW(char* sm, int m, int tid) {
#pragma unroll
    for (int i = 0; i < 4; i++) {
        int idx = i * 128 + tid;
        reinterpret_cast<uint4*>(sm + OBH)[idx] = g_wh4[m * 512 + idx];
        reinterpret_cast<uint4*>(sm + OBL)[idx] = g_wl4[m * 512 + idx];
    }
}

// convert 128 rows x 64 fp32 (row-major gmem) -> bf16 hi/lo SW128 smem tiles
__device__ __forceinline__ void convertX(char* sm, const float* __restrict__ src, int tid) {
#pragma unroll
    for (int i = 0; i < 8; i++) {
        int idx = i * 128 + tid;
        int r = idx >> 3, g = idx & 7;
        const float* p = src + r * 64 + g * 8;
        float4 f0 = ld4(p), f1 = ld4(p + 4);
        float vv[8] = {f0.x, f0.y, f0.z, f0.w, f1.x, f1.y, f1.z, f1.w};
        uint32_t hw[4], lw[4];
#pragma unroll
        for (int q = 0; q < 4; q++) split2(vv[2 * q], vv[2 * q + 1], hw[q], lw[q]);
        uint32_t off = swz((uint32_t)(r * 128 + g * 16));
        *reinterpret_cast<uint4*>(sm + OXH + off) = make_uint4(hw[0], hw[1], hw[2], hw[3]);
        *reinterpret_cast<uint4*>(sm + OXL + off) = make_uint4(lw[0], lw[1], lw[2], lw[3]);
    }
}

// ========================== setup: split weights ===========================
__global__ void kernelW(const float* __restrict__ w_m1, const float* __restrict__ w_m2,
                        const float* __restrict__ W_skip, const float* __restrict__ W_u1,
                        const float* __restrict__ W_u2) {
    int m = blockIdx.y;
    int idx = blockIdx.x * 256 + threadIdx.x;
    const float* W;
    switch (m) {
        case 0: W = w_m1; break;
        case 1: W = w_m1 + 4096; break;
        case 2: W = w_m2; break;
        case 3: W = w_m2 + 4096; break;
        case 4: W = W_skip; break;
        case 5: W = W_u1; break;
        default: W = W_u2; break;
    }
    float v = W[idx];
    int o = idx >> 6, k = idx & 63;
    __nv_bfloat16 h = __float2bfloat16(v);
    __nv_bfloat16 l = __float2bfloat16(v - __bfloat162float(h));
    uint32_t eoff = swz((uint32_t)(o * 128 + k * 2)) >> 1;
    reinterpret_cast<__nv_bfloat16*>(g_wh4)[m * 4096 + eoff] = h;
    reinterpret_cast<__nv_bfloat16*>(g_wl4)[m * 4096 + eoff] = l;
}

// ======= epilogue helpers =========
// store acc (+bias, relu) as split bf16 into HH/HL
__device__ __forceinline__ void epiH(char* sm, const float acc[2][8][4], const float* bias,
                                     int wid, int lane) {
    int g = lane >> 2, cb = (lane & 3) * 4;
#pragma unroll
    for (int m = 0; m < 2; m++)
#pragma unroll
        for (int rs = 0; rs < 2; rs++) {
            int row = wid * 32 + m * 16 + rs * 8 + g;
#pragma unroll
            for (int nt = 0; nt < 8; nt++) {
                int c = nt * 8 + (lane & 3) * 2;
                float v0 = fmaxf(acc[m][nt][rs * 2 + 0] + bias[c], 0.f);
                float v1 = fmaxf(acc[m][nt][rs * 2 + 1] + bias[c + 1], 0.f);
                uint32_t h, l;
                split2(v0, v1, h, l);
                uint32_t off = swz((uint32_t)(row * 128 + nt * 16 + cb));
                *reinterpret_cast<uint32_t*>(sm + OHH + off) = h;
                *reinterpret_cast<uint32_t*>(sm + OHL + off) = l;
            }
        }
}

// store acc (+bias, relu) TRANSPOSED per-block: dst[(c)*nsq + localRow], fp32
__device__ __forceinline__ void epiT(float* __restrict__ dst, int nsq, long localRow0,
                                     const float acc[2][8][4], const float* bias,
                                     int wid, int lane) {
    int g = lane >> 2;
#pragma unroll
    for (int m = 0; m < 2; m++)
#pragma unroll
        for (int rs = 0; rs < 2; rs++) {
            long rl = localRow0 + wid * 32 + m * 16 + rs * 8 + g;
#pragma unroll
            for (int nt = 0; nt < 8; nt++) {
                int c = nt * 8 + (lane & 3) * 2;
                dst[(long)c * nsq + rl] = fmaxf(acc[m][nt][rs * 2 + 0] + bias[c], 0.f);
                dst[(long)(c + 1) * nsq + rl] = fmaxf(acc[m][nt][rs * 2 + 1] + bias[c + 1], 0.f);
            }
        }
}

// store acc (+bias, no relu) row-major to gmem
__device__ __forceinline__ void epiG(float* __restrict__ dst, long row0,
                                     const float acc[2][8][4], const float* bias,
                                     int wid, int lane) {
    int g = lane >> 2;
#pragma unroll
    for (int m = 0; m < 2; m++)
#pragma unroll
        for (int rs = 0; rs < 2; rs++) {
            long row = row0 + wid * 32 + m * 16 + rs * 8 + g;
#pragma unroll
            for (int nt = 0; nt < 8; nt++) {
                int c = nt * 8 + (lane & 3) * 2;
                float v0 = acc[m][nt][rs * 2 + 0] + bias[c];
                float v1 = acc[m][nt][rs * 2 + 1] + bias[c + 1];
                *reinterpret_cast<float2*>(dst + row * 64 + c) = make_float2(v0, v1);
            }
        }
}

// =============== Kernel A: x -> m1t, m2t (2-layer MLPs), skip ==============
__global__ void __launch_bounds__(128) kernelA(
    const float* __restrict__ x,
    const float* __restrict__ b_m1, const float* __restrict__ b_m2,
    const float* __restrict__ b_skip) {
    extern __shared__ char sm[];
    uint32_t sb = smem_to_u32(sm);
    int tid = threadIdx.x, wid = tid >> 5, lane = tid & 31;
    long row0 = (long)blockIdx.x * 128;
    float* par = reinterpret_cast<float*>(sm + OPAR);

    // bucket mapping (all 128 rows lie in one graph-block: n^2 % 128 == 0)
    int n_, nsq;
    long bbase;
    if (row0 < 131072L)      { n_ = 32; bbase = 0L; }
    else if (row0 < 278528L) { n_ = 48; bbase = 131072L; }
    else if (row0 < 409600L) { n_ = 64; bbase = 278528L; }
    else                     { n_ = 96; bbase = 409600L; }
    nsq = n_ * n_;
    long blk_start = bbase + ((row0 - bbase) / nsq) * nsq;
    long localRow0 = row0 - blk_start;
    float* d1 = g_m1 + blk_start * 64;
    float* d2 = g_m2 + blk_start * 64;

    if (tid < 64) {
        par[tid] = b_m1[tid];
        par[64 + tid] = b_m1[64 + tid];
        par[128 + tid] = b_m2[tid];
        par[192 + tid] = b_m2[64 + tid];
        par[256 + tid] = b_skip[tid];
    }
    convertX(sm, x + row0 * 64, tid);
    copyW(sm, 0, tid);
    __syncthreads();

    float acc[2][8][4];

    // GEMM1: X @ Wm1_0 -> H (relu)
    warp_gemm(sb, OXH, OXL, acc, wid, lane);
    __syncthreads();
    epiH(sm, acc, par, wid, lane);
    copyW(sm, 1, tid);
    __syncthreads();

    // GEMM2: H @ Wm1_1 -> g_m1 transposed (relu)
    warp_gemm(sb, OHH, OHL, acc, wid, lane);
    __syncthreads();
    epiT(d1, nsq, localRow0, acc, par + 64, wid, lane);
    copyW(sm, 2, tid);
    __syncthreads();

    // GEMM3: X @ Wm2_0 -> H (relu)
    warp_gemm(sb, OXH, OXL, acc, wid, lane);
    __syncthreads();
    epiH(sm, acc, par + 128, wid, lane);
    copyW(sm, 3, tid);
    __syncthreads();

    // GEMM4: H @ Wm2_1 -> g_m2 transposed (relu)
    warp_gemm(sb, OHH, OHL, acc, wid, lane);
    __syncthreads();
    epiT(d2, nsq, localRow0, acc, par + 192, wid, lane);
    copyW(sm, 4, tid);
    __syncthreads();

    // GEMM5: X @ W_skip -> g_hs2 (no relu, row-major)
    warp_gemm(sb, OXH, OXL, acc, wid, lane);
    epiG(g_hs2, row0, acc, par + 256, wid, lane);
}

// ---------------------------------------------------------------------------
// Kernel B (tensor-core): per-graph-block, per-channel spatial matmul
//   h[b,i,k,c] = sum_j m1[b,i,j,c]*m2[b,j,k,c];  g_hs2 += h
// CTA = (block b, 32x32 i/k tile, 8 channels). Warp w owns channel w.
// A/B tiles staged as bf16 hi/lo, 2 rows packed per 128B SW128 row.
// smem: Ah[8ch][2KB] @0, Al @16K, Bh @32K, Bl @48K; Cs (fp32 [8][32][33]) @0.
// ---------------------------------------------------------------------------
#define BAH 0
#define BAL 16384
#define BBH 32768
#define BBL 49152

template <int N>
__global__ void __launch_bounds__(256) kernelB(long baseRow) {
    constexpr int NT = (N + 31) / 32;
    extern __shared__ char sm[];
    uint32_t sb = smem_to_u32(sm);
    int t = threadIdx.x, lane = t & 31, wid = t >> 5;
    int b = blockIdx.x;
    int ti = blockIdx.y / NT, tk = blockIdx.y % NT;
    int cg = blockIdx.z;                       // channel group 0..7 (8 ch each)
    int i0 = ti * 32, k0 = tk * 32;
    long blk = baseRow + (long)b * (N * N);
    const float* m1p = g_m1 + blk * 64;
    const float* m2p = g_m2 + blk * 64;

    int sr = t & 31, sch = t >> 5;             // staging: row, channel
    int cth = cg * 8 + sch;
    uint32_t rowoff = (uint32_t)((sr >> 1) * 128 + (sr & 1) * 64);
    uint32_t sA = (uint32_t)(sch * 2048);
    const int nk = (k0 + 32 <= N) ? 32 : (N - k0);

    float acc[2][4][4];
#pragma unroll
    for (int m = 0; m < 2; m++)
#pragma unroll
        for (int n8 = 0; n8 < 4; n8++)
#pragma unroll
            for (int q = 0; q < 4; q++) acc[m][n8][q] = 0.f;

#pragma unroll
    for (int jc = 0; jc < NT; jc++) {
        const int j0 = jc * 32;
        const int nj = (j0 + 32 <= N) ? 32 : (N - j0);
        __syncthreads();
        // ---- stage A (i-rows, j-window) ----
        {
            float4 f[8];
#pragma unroll
            for (int q = 0; q < 8; q++) f[q] = make_float4(0.f, 0.f, 0.f, 0.f);
            if (i0 + sr < N) {
                const float* p = m1p + (long)cth * (N * N) + (long)(i0 + sr) * N + j0;
#pragma unroll
                for (int q = 0; q < 8; q++)
                    if (q * 4 < nj) f[q] = ld4(p + q * 4);
            }
            uint32_t h[16], l[16];
#pragma unroll
            for (int q = 0; q < 8; q++) {
                split2(f[q].x, f[q].y, h[2 * q], l[2 * q]);
                split2(f[q].z, f[q].w, h[2 * q + 1], l[2 * q + 1]);
            }
#pragma unroll
            for (int g = 0; g < 4; g++) {
                uint32_t off = sA + swz(rowoff + g * 16);
                *reinterpret_cast<uint4*>(sm + BAH + off) =
                    make_uint4(h[4 * g], h[4 * g + 1], h[4 * g + 2], h[4 * g + 3]);
                *reinterpret_cast<uint4*>(sm + BAL + off) =
                    make_uint4(l[4 * g], l[4 * g + 1], l[4 * g + 2], l[4 * g + 3]);
            }
        }
        // ---- stage B (j-rows, k-window) ----
        {
            float4 f[8];
#pragma unroll
            for (int q = 0; q < 8; q++) f[q] = make_float4(0.f, 0.f, 0.f, 0.f);
            if (j0 + sr < N) {
                const float* p = m2p + (long)cth * (N * N) + (long)(j0 + sr) * N + k0;
#pragma unroll
                for (int q = 0; q < 8; q++)
                    if (q * 4 < nk) f[q] = ld4(p + q * 4);
            }
            uint32_t h[16], l[16];
#pragma unroll
            for (int q = 0; q < 8; q++) {
                split2(f[q].x, f[q].y, h[2 * q], l[2 * q]);
                split2(f[q].z, f[q].w, h[2 * q + 1], l[2 * q + 1]);
            }
#pragma unroll
            for (int g = 0; g < 4; g++) {
                uint32_t off = sA + swz(rowoff + g * 16);
                *reinterpret_cast<uint4*>(sm + BBH + off) =
                    make_uint4(h[4 * g], h[4 * g + 1], h[4 * g + 2], h[4 * g + 3]);
                *reinterpret_cast<uint4*>(sm + BBL + off) =
                    make_uint4(l[4 * g], l[4 * g + 1], l[4 * g + 2], l[4 * g + 3]);
            }
        }
        __syncthreads();
        // ---- MMA: warp wid computes channel wid's 32x32 tile over K=32 ----
        {
            uint32_t aH = sb + BAH + wid * 2048, aL = sb + BAL + wid * 2048;
            uint32_t bH = sb + BBH + wid * 2048, bL = sb + BBL + wid * 2048;
#pragma unroll
            for (int ks = 0; ks < 2; ks++) {
                uint32_t ah[2][4], al[2][4];
#pragma unroll
                for (int m = 0; m < 2; m++) {
                    int ri = m * 16 + (lane & 15);
                    uint32_t offA = swz((uint32_t)((ri >> 1) * 128 + (ri & 1) * 64 +
                                                   (ks * 2 + (lane >> 4)) * 16));
                    ldsm_x4(ah[m], aH + offA);
                    ldsm_x4(al[m], aL + offA);
                }
#pragma unroll
                for (int nb = 0; nb < 2; nb++) {
                    int jr = ks * 16 + (lane & 15);
                    uint32_t offB = swz((uint32_t)((jr >> 1) * 128 + (jr & 1) * 64 +
                                                   (nb * 2 + (lane >> 4)) * 16));
                    uint32_t bh[4], bl[4];
                    ldsm_x4_t(bh, bH + offB);
                    ldsm_x4_t(bl, bL + offB);
#pragma unroll
                    for (int m = 0; m < 2; m++) {
                        mma16816(acc[m][nb * 2 + 0], ah[m], &bh[0]);
                        mma16816(acc[m][nb * 2 + 0], al[m], &bh[0]);
                        mma16816(acc[m][nb * 2 + 0], ah[m], &bl[0]);
                        mma16816(acc[m][nb * 2 + 1], ah[m], &bh[2]);
                        mma16816(acc[m][nb * 2 + 1], al[m], &bh[2]);
                        mma16816(acc[m][nb * 2 + 1], ah[m], &bl[2]);
                    }
                }
            }
        }
    }
    __syncthreads();
    // ---- stage C tiles (fp32) into smem: Cs[ch][i][k], stride 33 ----
    float* Cs = reinterpret_cast<float*>(sm);
    {
        int g = lane >> 2, cbl = (lane & 3) * 2;
#pragma unroll
        for (int m = 0; m < 2; m++)
#pragma unroll
            for (int n8 = 0; n8 < 4; n8++)
#pragma unroll
                for (int rs = 0; rs < 2; rs++) {
                    int r = m * 16 + rs * 8 + g;
                    Cs[wid * 1056 + r * 33 + n8 * 8 + cbl + 0] = acc[m][n8][rs * 2 + 0];
                    Cs[wid * 1056 + r * 33 + n8 * 8 + cbl + 1] = acc[m][n8][rs * 2 + 1];
                }
    }
    __syncthreads();
    // ---- coalesced RMW into g_hs2: 8 consecutive channels = 32B sectors ----
#pragma unroll
    for (int it = 0; it < 4; it++) {
        int ik = it * 256 + t;
        int i = ik >> 5, k = ik & 31;
        if (i0 + i < N && k0 + k < N) {
            float* p = g_hs2 + (blk + (long)(i0 + i) * N + (k0 + k)) * 64 + cg * 8;
            float v[8];
#pragma unroll
            for (int ch = 0; ch < 8; ch++) v[ch] = Cs[ch * 1056 + i * 33 + k];
            float4 r0 = ld4(p), r1 = ld4(p + 4);
            r0.x += v[0]; r0.y += v[1]; r0.z += v[2]; r0.w += v[3];
            r1.x += v[4]; r1.y += v[5]; r1.z += v[6]; r1.w += v[7];
            st4(p, r0); st4(p + 4, r1);
        }
    }
}

// ======== Kernel C: hs2 -> Lin+BN+ReLU -> Lin+BN+ReLU -> +hs2 -> out ========
__global__ void __launch_bounds__(128) kernelC(
    const float* __restrict__ b_u1, const float* __restrict__ g1,
    const float* __restrict__ beta1, const float* __restrict__ rm1,
    const float* __restrict__ rv1,
    const float* __restrict__ b_u2, const float* __restrict__ g2,
    const float* __restrict__ beta2, const float* __restrict__ rm2,
    const float* __restrict__ rv2,
    float* __restrict__ out) {
    extern __shared__ char sm[];
    uint32_t sb = smem_to_u32(sm);
    int tid = threadIdx.x, wid = tid >> 5, lane = tid & 31;
    long row0 = (long)blockIdx.x * 128;
    float* par = reinterpret_cast<float*>(sm + OPAR);

    if (tid < 64) {
        par[tid] = b_u1[tid];
        float sc1 = g1[tid] * rsqrtf(rv1[tid] + 1e-5f);
        par[64 + tid] = sc1;
        par[128 + tid] = beta1[tid] - rm1[tid] * sc1;
        par[192 + tid] = b_u2[tid];
        float sc2 = g2[tid] * rsqrtf(rv2[tid] + 1e-5f);
        par[256 + tid] = sc2;
        par[320 + tid] = beta2[tid] - rm2[tid] * sc2;
    }
    convertX(sm, g_hs2 + row0 * 64, tid);
    copyW(sm, 5, tid);
    __syncthreads();

    float acc[2][8][4];

    // GEMM1: hs2 @ W_u1 -> H = relu(bn1(. + b_u1))
    warp_gemm(sb, OXH, OXL, acc, wid, lane);
    __syncthreads();
    {
        int g = lane >> 2, cb = (lane & 3) * 4;
#pragma unroll
        for (int m = 0; m < 2; m++)
#pragma unroll
            for (int rs = 0; rs < 2; rs++) {
                int row = wid * 32 + m * 16 + rs * 8 + g;
#pragma unroll
                for (int nt = 0; nt < 8; nt++) {
                    int c = nt * 8 + (lane & 3) * 2;
                    float v0 = fmaxf((acc[m][nt][rs * 2 + 0] + par[c]) * par[64 + c] + par[128 + c], 0.f);
                    float v1 = fmaxf((acc[m][nt][rs * 2 + 1] + par[c + 1]) * par[64 + c + 1] + par[128 + c + 1], 0.f);
                    uint32_t h, l;
                    split2(v0, v1, h, l);
                    uint32_t off = swz((uint32_t)(row * 128 + nt * 16 + cb));
                    *reinterpret_cast<uint32_t*>(sm + OHH + off) = h;
                    *reinterpret_cast<uint32_t*>(sm + OHL + off) = l;
                }
            }
    }
    copyW(sm, 6, tid);
    __syncthreads();

    // GEMM2: H @ W_u2 -> out = relu(bn2(. + b_u2)) + hs2
    warp_gemm(sb, OHH, OHL, acc, wid, lane);
    {
        int g = lane >> 2, cb = (lane & 3) * 4;
#pragma unroll
        for (int m = 0; m < 2; m++)
#pragma unroll
            for (int rs = 0; rs < 2; rs++) {
                int row = wid * 32 + m * 16 + rs * 8 + g;
                long grow = row0 + row;
#pragma unroll
                for (int nt = 0; nt < 8; nt++) {
                    int c = nt * 8 + (lane & 3) * 2;
                    float u0 = fmaxf((acc[m][nt][rs * 2 + 0] + par[192 + c]) * par[256 + c] + par[320 + c], 0.f);
                    float u1 = fmaxf((acc[m][nt][rs * 2 + 1] + par[192 + c + 1]) * par[256 + c + 1] + par[320 + c + 1], 0.f);
                    uint32_t off = swz((uint32_t)(row * 128 + nt * 16 + cb));
                    uint32_t xh = *reinterpret_cast<uint32_t*>(sm + OXH + off);
                    uint32_t xl = *reinterpret_cast<uint32_t*>(sm + OXL + off);
                    float2 h2 = __bfloat1622float2(*reinterpret_cast<__nv_bfloat162*>(&xh));
                    float2 l2 = __bfloat1622float2(*reinterpret_cast<__nv_bfloat162*>(&xl));
                    *reinterpret_cast<float2*>(out + grow * 64 + c) =
                        make_float2(u0 + (h2.x + l2.x), u1 + (h2.y + l2.y));
                }
            }
    }
}

// ---------------------------------------------------------------------------
extern "C" void kernel_launch(void* const* d_in, const int* in_sizes, int n_in,
                              void* d_out, int out_size) {
    (void)in_sizes; (void)n_in; (void)out_size;
    const float* x      = (const float*)d_in[0];
    const float* w_m1   = (const float*)d_in[1];
    const float* b_m1   = (const float*)d_in[2];
    const float* w_m2   = (const float*)d_in[3];
    const float* b_m2   = (const float*)d_in[4];
    const float* W_skip = (const float*)d_in[5];
    const float* b_skip = (const float*)d_in[6];
    const float* W_u1   = (const float*)d_in[7];
    const float* b_u1   = (const float*)d_in[8];
    const float* g1     = (const float*)d_in[9];
    const float* beta1  = (const float*)d_in[10];
    const float* rm1    = (const float*)d_in[11];
    const float* rv1    = (const float*)d_in[12];
    const float* W_u2   = (const float*)d_in[13];
    const float* b_u2   = (const float*)d_in[14];
    const float* g2     = (const float*)d_in[15];
    const float* beta2  = (const float*)d_in[16];
    const float* rm2    = (const float*)d_in[17];
    const float* rv2    = (const float*)d_in[18];
    float* out = (float*)d_out;

    cudaFuncSetAttribute(kernelA, cudaFuncAttributeMaxDynamicSharedMemorySize, SMEM_BYTES);
    cudaFuncSetAttribute(kernelC, cudaFuncAttributeMaxDynamicSharedMemorySize, SMEM_BYTES);
    cudaFuncSetAttribute(kernelB<32>, cudaFuncAttributeMaxDynamicSharedMemorySize, 65536);
    cudaFuncSetAttribute(kernelB<48>, cudaFuncAttributeMaxDynamicSharedMemorySize, 65536);
    cudaFuncSetAttribute(kernelB<64>, cudaFuncAttributeMaxDynamicSharedMemorySize, 65536);
    cudaFuncSetAttribute(kernelB<96>, cudaFuncAttributeMaxDynamicSharedMemorySize, 65536);

    kernelW<<<dim3(16, 7), 256>>>(w_m1, w_m2, W_skip, W_u1, W_u2);

    kernelA<<<N_TOTAL / 128, 128, SMEM_BYTES>>>(x, b_m1, b_m2, b_skip);

    // BLOCKS = [(128,32),(64,48),(32,64),(16,96)], row bases 0/131072/278528/409600
    kernelB<32><<<dim3(128, 1, 8), 256, 65536>>>(0L);
    kernelB<48><<<dim3(64, 4, 8), 256, 65536>>>(131072L);
    kernelB<64><<<dim3(32, 4, 8), 256, 65536>>>(278528L);
    kernelB<96><<<dim3(16, 9, 8), 256, 65536>>>(409600L);

    kernelC<<<N_TOTAL / 128, 128, SMEM_BYTES>>>(b_u1, g1, beta1, rm1, rv1,
                                                b_u2, g2, beta2, rm2, rv2, out);
}